// round 7
// baseline (speedup 1.0000x reference)
#include <cuda_runtime.h>
#include <cuda_fp16.h>
#include <math.h>

#define HDIM 384
#define WDIM 384
#define HW (HDIM*WDIM)            // 147456
#define SUMN 128
#define BATCH 16
#define LAG 8
#define NEGV -1000000000.0f
#define BLOCKS_PER_IMG 72         // 147456 / (256*8)
#define WTILES 144                // 147456 / (256*4)

// Scratch (no cudaMalloc allowed)
__device__ __half g_conf[(size_t)SUMN * HW];   // 37.7 MB
__device__ float g_meanconf[SUMN];
__device__ float g_overlap[SUMN];
__device__ float g_demand[BATCH];

__device__ __forceinline__ float blockReduceSum256(float v) {
    __shared__ float ws[8];
    for (int o = 16; o > 0; o >>= 1) v += __shfl_down_sync(0xffffffffu, v, o);
    int lane = threadIdx.x & 31, wid = threadIdx.x >> 5;
    if (lane == 0) ws[wid] = v;
    __syncthreads();
    float r = 0.0f;
    if (wid == 0) {
        r = (lane < 8) ? ws[lane] : 0.0f;
        for (int o = 4; o > 0; o >>= 1) r += __shfl_down_sync(0xffffffffu, r, o);
    }
    __syncthreads();   // safe reuse of ws on next call
    return r;  // valid in thread 0
}

__global__ void k_zero() {
    int t = threadIdx.x;
    if (t < SUMN) { g_meanconf[t] = 0.0f; g_overlap[t] = 0.0f; }
    if (t < BATCH) g_demand[t] = 0.0f;
}

// Kernel 1: conf = sigmoid(max(ch0, ch1)) -> fp16; accumulate mean_conf[n], demand[b]
__global__ void __launch_bounds__(256) k_conf(const float* __restrict__ psm,
                                              const float* __restrict__ req) {
    int n    = blockIdx.x / BLOCKS_PER_IMG;
    int tile = blockIdx.x % BLOCKS_PER_IMG;
    int p0   = tile * 2048 + threadIdx.x * 8;

    const float* base0 = psm + (size_t)n * 2 * HW + p0;
    const float4 a4l = *(const float4*)(base0);
    const float4 a4h = *(const float4*)(base0 + 4);
    const float4 b4l = *(const float4*)(base0 + HW);
    const float4 b4h = *(const float4*)(base0 + HW + 4);
    float a[8] = {a4l.x, a4l.y, a4l.z, a4l.w, a4h.x, a4h.y, a4h.z, a4h.w};
    float b[8] = {b4l.x, b4l.y, b4l.z, b4l.w, b4h.x, b4h.y, b4h.z, b4h.w};

    __half hs[8];
    float sum = 0.0f;
    #pragma unroll
    for (int u = 0; u < 8; u++) {
        float m = fmaxf(a[u], b[u]);
        float s = __fdividef(1.0f, 1.0f + __expf(-m));
        hs[u] = __float2half_rn(s);
        sum += s;
    }
    *(uint4*)(g_conf + (size_t)n * HW + p0) = *(const uint4*)hs;

    float dsum = 0.0f;
    bool ego = ((n & (LAG - 1)) == 0);
    if (ego) {
        const float* rbase = req + (size_t)n * HW + p0;
        const float4 r4l = *(const float4*)(rbase);
        const float4 r4h = *(const float4*)(rbase + 4);
        dsum = r4l.x + r4l.y + r4l.z + r4l.w + r4h.x + r4h.y + r4h.z + r4h.w;
    }

    float bs = blockReduceSum256(sum);
    if (threadIdx.x == 0) atomicAdd(&g_meanconf[n], bs);
    if (ego) {
        float bd = blockReduceSum256(dsum);
        if (threadIdx.x == 0) atomicAdd(&g_demand[n >> 3], bd);
    }
}

// Kernel 2 v2: one block per (batch, tile). Di loaded ONCE, reused for all 8 peers.
__global__ void __launch_bounds__(256) k_warp(const float* __restrict__ req,
                                              const float* __restrict__ na) {
    int b    = blockIdx.x / WTILES;
    int tile = blockIdx.x % WTILES;
    int t = threadIdx.x;

    __shared__ float sA[48];
    if (t < 48) {
        int l = t / 6, e = t % 6;
        sA[t] = na[(size_t)((b * LAG + 0) * LAG + l) * 6 + e];
    }

    int p0 = tile * 1024 + t * 4;
    const float4 d4 = *(const float4*)(req + (size_t)(b * LAG) * HW + p0);
    float di[4] = {d4.x, d4.y, d4.z, d4.w};

    const float step = 2.0f / 383.0f;
    float fgx[4], fgy[4];
    #pragma unroll
    for (int u = 0; u < 4; u++) {
        int p = p0 + u;
        int i = p / WDIM;
        int j = p - i * WDIM;
        fgx[u] = fmaf((float)j, step, -1.0f);
        fgy[u] = fmaf((float)i, step, -1.0f);
    }
    __syncthreads();

    float res[LAG];
    #pragma unroll
    for (int l = 0; l < LAG; l++) {
        float A00 = sA[l*6+0], A01 = sA[l*6+1], A02 = sA[l*6+2];
        float A10 = sA[l*6+3], A11 = sA[l*6+4], A12 = sA[l*6+5];
        const __half* cimg = g_conf + (size_t)(b * LAG + l) * HW;

        float sum = 0.0f;
        #pragma unroll
        for (int u = 0; u < 4; u++) {
            float sx = fmaf(A00, fgx[u], fmaf(A01, fgy[u], A02));
            float sy = fmaf(A10, fgx[u], fmaf(A11, fgy[u], A12));
            float px = (sx + 1.0f) * (0.5f * (WDIM - 1));
            float py = (sy + 1.0f) * (0.5f * (HDIM - 1));
            float x0f = floorf(px), y0f = floorf(py);
            float wx = px - x0f, wy = py - y0f;
            int x0 = (int)x0f, y0 = (int)y0f;

            float v00 = 0.0f, v01 = 0.0f, v10 = 0.0f, v11 = 0.0f;
            bool xv0 = (unsigned)x0 < (unsigned)WDIM;
            bool xv1 = (unsigned)(x0 + 1) < (unsigned)WDIM;
            bool yv0 = (unsigned)y0 < (unsigned)HDIM;
            bool yv1 = (unsigned)(y0 + 1) < (unsigned)HDIM;
            if (yv0) {
                const __half* row = cimg + (size_t)y0 * WDIM;
                if (xv0) v00 = __half2float(__ldg(row + x0));
                if (xv1) v01 = __half2float(__ldg(row + x0 + 1));
            }
            if (yv1) {
                const __half* row = cimg + (size_t)(y0 + 1) * WDIM;
                if (xv0) v10 = __half2float(__ldg(row + x0));
                if (xv1) v11 = __half2float(__ldg(row + x0 + 1));
            }
            float top = v00 * (1.0f - wx) + v01 * wx;
            float bot = v10 * (1.0f - wx) + v11 * wx;
            float val = top * (1.0f - wy) + bot * wy;
            sum += di[u] * val;
        }
        res[l] = sum;
    }

    #pragma unroll
    for (int l = 0; l < LAG; l++) {
        float bs = blockReduceSum256(res[l]);
        if (t == 0) atomicAdd(&g_overlap[b * LAG + l], bs);
    }
}

// Kernel 3 v3: one block per row r, 128 threads. Weights staged in dynamic smem.
// Warps 0-1 compute the q-path, warps 2-3 compute the k-path, concurrently.
#define NW_QW1 512
#define NW_QW2 4096
#define NW_KW1 512
#define NW_KW2 4096
#define NW_EW1 8192
#define NW_EW2 64
#define NW_TOTAL (NW_QW1+NW_QW2+NW_KW1+NW_KW2+NW_EW1+NW_EW2)   // 17472 floats

__global__ void __launch_bounds__(128)
k_head(const float* __restrict__ na,
       const float* __restrict__ qW1, const float* __restrict__ qb1,
       const float* __restrict__ qW2, const float* __restrict__ qb2,
       const float* __restrict__ kW1, const float* __restrict__ kb1,
       const float* __restrict__ kW2, const float* __restrict__ kb2,
       const float* __restrict__ eW1, const float* __restrict__ eb1,
       const float* __restrict__ eW2, const float* __restrict__ eb2,
       float* __restrict__ out) {
    extern __shared__ float sw[];
    float* w_qW1 = sw;
    float* w_qW2 = w_qW1 + NW_QW1;
    float* w_kW1 = w_qW2 + NW_QW2;
    float* w_kW2 = w_kW1 + NW_KW1;
    float* w_eW1 = w_kW2 + NW_KW2;
    float* w_eW2 = w_eW1 + NW_EW1;

    __shared__ float s_ego[8], s_feat[8];
    __shared__ float s_hq[64], s_hk[64], s_q[64], s_k[64];
    __shared__ float s_pq[64], s_pk[64];
    __shared__ float s_ws[2];

    int r = blockIdx.x;
    int b = r >> 3, l = r & (LAG - 1);
    int t = threadIdx.x;

    // Stage all weights (cooperative float4 streams)
    {
        #pragma unroll
        for (int i = t * 4; i < NW_QW1; i += 512) *(float4*)(w_qW1 + i) = *(const float4*)(qW1 + i);
        #pragma unroll
        for (int i = t * 4; i < NW_KW1; i += 512) *(float4*)(w_kW1 + i) = *(const float4*)(kW1 + i);
        for (int i = t * 4; i < NW_QW2; i += 512) *(float4*)(w_qW2 + i) = *(const float4*)(qW2 + i);
        for (int i = t * 4; i < NW_KW2; i += 512) *(float4*)(w_kW2 + i) = *(const float4*)(kW2 + i);
        for (int i = t * 4; i < NW_EW1; i += 512) *(float4*)(w_eW1 + i) = *(const float4*)(eW1 + i);
        if (t < 16) *(float4*)(w_eW2 + t * 4) = *(const float4*)(eW2 + t * 4);
    }

    const float invHW = 1.0f / (float)HW;
    if (t == 0) {
        float dm  = g_demand[b] * invHW;
        float mc0 = g_meanconf[b * LAG] * invHW;
        s_ego[0] = mc0; s_ego[1] = dm; s_ego[2] = 0.0f; s_ego[3] = 0.0f;
        s_ego[4] = 1.0f; s_ego[5] = 0.0f; s_ego[6] = 0.0f; s_ego[7] = dm;

        float mc = g_meanconf[r] * invHW;
        float ov = g_overlap[r] * invHW;
        const float* A = na + (size_t)((b * LAG + 0) * LAG + l) * 6;
        float dx = A[2], dy = A[5];
        float dist = sqrtf(dx * dx + dy * dy);
        const float* D  = na + (size_t)((b * LAG + l) * LAG + l) * 6;
        const float* D0 = na + (size_t)((b * LAG + 0) * LAG + 0) * 6;
        float yaw  = atan2f(D[3], D[0]);
        float yaw0 = atan2f(D0[3], D0[0]);
        float d = yaw0 - yaw;
        s_feat[0] = mc; s_feat[1] = ov; s_feat[2] = dx; s_feat[3] = dy;
        s_feat[4] = cosf(d); s_feat[5] = sinf(d); s_feat[6] = dist; s_feat[7] = dm;
    }
    __syncthreads();

    int j = t & 63;
    bool qpath = (t < 64);

    // Layer 1 (8-wide)
    {
        const float* w = qpath ? w_qW1 : w_kW1;
        const float* bias = qpath ? qb1 : kb1;
        const float* x = qpath ? s_ego : s_feat;
        float acc = bias[j];
        #pragma unroll
        for (int i = 0; i < 8; i++) acc = fmaf(x[i], w[i * 64 + j], acc);
        (qpath ? s_hq : s_hk)[j] = fmaxf(acc, 0.0f);
    }
    __syncthreads();

    // Layer 2 (64-wide)
    {
        const float* w = qpath ? w_qW2 : w_kW2;
        const float* bias = qpath ? qb2 : kb2;
        const float* x = qpath ? s_hq : s_hk;
        float acc = bias[j];
        #pragma unroll
        for (int i = 0; i < 64; i++) acc = fmaf(x[i], w[i * 64 + j], acc);
        (qpath ? s_q : s_k)[j] = acc;
    }
    __syncthreads();

    // e-layer hidden: split the 128-wide dot between the two halves
    {
        const float* x = qpath ? s_q : s_k;
        const float* w = qpath ? w_eW1 : (w_eW1 + 64 * 64);
        float acc = qpath ? eb1[j] : 0.0f;
        #pragma unroll
        for (int i = 0; i < 64; i++) acc = fmaf(x[i], w[i * 64 + j], acc);
        (qpath ? s_pq : s_pk)[j] = acc;
    }
    __syncthreads();

    // Final: relu, dot with eW2, reduce over 64 (2 warps)
    if (t < 64) {
        float eh = fmaxf(s_pq[j] + s_pk[j], 0.0f) * w_eW2[j];
        for (int o = 16; o > 0; o >>= 1) eh += __shfl_down_sync(0xffffffffu, eh, o);
        if ((t & 31) == 0) s_ws[t >> 5] = eh;
    }
    __syncthreads();
    if (t == 0) {
        float logit = s_ws[0] + s_ws[1] + eb2[0];
        if (l == 0) logit = NEGV;
        float s = 1.0f / (1.0f + expf(-logit));
        out[r] = fminf(fmaxf(s, 0.0f), 1.0f);
    }
}

extern "C" void kernel_launch(void* const* d_in, const int* in_sizes, int n_in,
                              void* d_out, int out_size) {
    const float* psm  = (const float*)d_in[0];
    const float* req  = (const float*)d_in[1];
    const float* na   = (const float*)d_in[2];
    // d_in[3] = record_len (unused, always L)
    const float* qW1 = (const float*)d_in[4];
    const float* qb1 = (const float*)d_in[5];
    const float* qW2 = (const float*)d_in[6];
    const float* qb2 = (const float*)d_in[7];
    const float* kW1 = (const float*)d_in[8];
    const float* kb1 = (const float*)d_in[9];
    const float* kW2 = (const float*)d_in[10];
    const float* kb2 = (const float*)d_in[11];
    const float* eW1 = (const float*)d_in[12];
    const float* eb1 = (const float*)d_in[13];
    const float* eW2 = (const float*)d_in[14];
    const float* eb2 = (const float*)d_in[15];
    float* out = (float*)d_out;

    cudaFuncSetAttribute(k_head, cudaFuncAttributeMaxDynamicSharedMemorySize,
                         NW_TOTAL * 4);

    k_zero<<<1, 256>>>();
    k_conf<<<SUMN * BLOCKS_PER_IMG, 256>>>(psm, req);
    k_warp<<<BATCH * WTILES, 256>>>(req, na);
    k_head<<<SUMN, 128, NW_TOTAL * 4>>>(na, qW1, qb1, qW2, qb2, kW1, kb1, kW2, kb2,
                                        eW1, eb1, eW2, eb2, out);
}

// round 9
// speedup vs baseline: 1.0857x; 1.0857x over previous
#include <cuda_runtime.h>
#include <cuda_fp16.h>
#include <math.h>

#define HDIM 384
#define WDIM 384
#define HW (HDIM*WDIM)            // 147456
#define SUMN 128
#define BATCH 16
#define LAG 8
#define NEGV -1000000000.0f
#define CTILES 72                 // 147456 / (256*8)
#define WTILES 144                // 147456 / (256*4)

// Scratch (no cudaMalloc allowed)
__device__ __half g_conf[(size_t)SUMN * HW];   // 37.7 MB
__device__ float g_pmc[SUMN * CTILES];         // mean_conf partials
__device__ float g_pov[SUMN * WTILES];         // overlap partials
__device__ float g_pdem[BATCH * CTILES];       // demand partials

__device__ __forceinline__ float blockReduceSum256(float v) {
    __shared__ float ws[8];
    for (int o = 16; o > 0; o >>= 1) v += __shfl_down_sync(0xffffffffu, v, o);
    int lane = threadIdx.x & 31, wid = threadIdx.x >> 5;
    if (lane == 0) ws[wid] = v;
    __syncthreads();
    float r = 0.0f;
    if (wid == 0) {
        r = (lane < 8) ? ws[lane] : 0.0f;
        for (int o = 4; o > 0; o >>= 1) r += __shfl_down_sync(0xffffffffu, r, o);
    }
    __syncthreads();
    return r;  // valid in thread 0
}

// Kernel 1: conf = sigmoid(max(ch0, ch1)) -> fp16; partial sums (no atomics)
__global__ void __launch_bounds__(256) k_conf(const float* __restrict__ psm,
                                              const float* __restrict__ req) {
    int n    = blockIdx.x / CTILES;
    int tile = blockIdx.x % CTILES;
    int p0   = tile * 2048 + threadIdx.x * 8;

    const float* base0 = psm + (size_t)n * 2 * HW + p0;
    const float4 a4l = *(const float4*)(base0);
    const float4 a4h = *(const float4*)(base0 + 4);
    const float4 b4l = *(const float4*)(base0 + HW);
    const float4 b4h = *(const float4*)(base0 + HW + 4);
    float a[8] = {a4l.x, a4l.y, a4l.z, a4l.w, a4h.x, a4h.y, a4h.z, a4h.w};
    float b[8] = {b4l.x, b4l.y, b4l.z, b4l.w, b4h.x, b4h.y, b4h.z, b4h.w};

    __half hs[8];
    float sum = 0.0f;
    #pragma unroll
    for (int u = 0; u < 8; u++) {
        float m = fmaxf(a[u], b[u]);
        float s = __fdividef(1.0f, 1.0f + __expf(-m));
        hs[u] = __float2half_rn(s);
        sum += s;
    }
    *(uint4*)(g_conf + (size_t)n * HW + p0) = *(const uint4*)hs;

    float dsum = 0.0f;
    bool ego = ((n & (LAG - 1)) == 0);
    if (ego) {
        const float* rbase = req + (size_t)n * HW + p0;
        const float4 r4l = *(const float4*)(rbase);
        const float4 r4h = *(const float4*)(rbase + 4);
        dsum = r4l.x + r4l.y + r4l.z + r4l.w + r4h.x + r4h.y + r4h.z + r4h.w;
    }

    float bs = blockReduceSum256(sum);
    if (threadIdx.x == 0) g_pmc[n * CTILES + tile] = bs;
    if (ego) {
        float bd = blockReduceSum256(dsum);
        if (threadIdx.x == 0) g_pdem[(n >> 3) * CTILES + tile] = bd;
    }
}

// Kernel 2: per-(image,tile) blocks (L1-friendly). Partial overlap sums, no atomics.
__global__ void __launch_bounds__(256) k_warp(const float* __restrict__ req,
                                              const float* __restrict__ na) {
    int n    = blockIdx.x / WTILES;
    int tile = blockIdx.x % WTILES;
    int b = n >> 3, l = n & (LAG - 1);

    const float* A = na + (size_t)((b * LAG + 0) * LAG + l) * 6;
    float A00 = __ldg(A + 0), A01 = __ldg(A + 1), A02 = __ldg(A + 2);
    float A10 = __ldg(A + 3), A11 = __ldg(A + 4), A12 = __ldg(A + 5);

    const __half* cimg = g_conf + (size_t)n * HW;
    int p0 = tile * 1024 + threadIdx.x * 4;
    const float4 d4 = *(const float4*)(req + (size_t)(b * LAG) * HW + p0);
    float di[4] = {d4.x, d4.y, d4.z, d4.w};

    const float step = 2.0f / 383.0f;
    float sum = 0.0f;
    #pragma unroll
    for (int u = 0; u < 4; u++) {
        int p = p0 + u;
        int i = p / WDIM;
        int j = p - i * WDIM;
        float gx = fmaf((float)j, step, -1.0f);
        float gy = fmaf((float)i, step, -1.0f);
        float sx = fmaf(A00, gx, fmaf(A01, gy, A02));
        float sy = fmaf(A10, gx, fmaf(A11, gy, A12));
        float px = (sx + 1.0f) * (0.5f * (WDIM - 1));
        float py = (sy + 1.0f) * (0.5f * (HDIM - 1));
        float x0f = floorf(px), y0f = floorf(py);
        float wx = px - x0f, wy = py - y0f;
        int x0 = (int)x0f, y0 = (int)y0f;

        float v00 = 0.0f, v01 = 0.0f, v10 = 0.0f, v11 = 0.0f;
        bool xv0 = (unsigned)x0 < (unsigned)WDIM;
        bool xv1 = (unsigned)(x0 + 1) < (unsigned)WDIM;
        bool yv0 = (unsigned)y0 < (unsigned)HDIM;
        bool yv1 = (unsigned)(y0 + 1) < (unsigned)HDIM;
        if (yv0) {
            const __half* row = cimg + (size_t)y0 * WDIM;
            if (xv0) v00 = __half2float(__ldg(row + x0));
            if (xv1) v01 = __half2float(__ldg(row + x0 + 1));
        }
        if (yv1) {
            const __half* row = cimg + (size_t)(y0 + 1) * WDIM;
            if (xv0) v10 = __half2float(__ldg(row + x0));
            if (xv1) v11 = __half2float(__ldg(row + x0 + 1));
        }
        float top = v00 * (1.0f - wx) + v01 * wx;
        float bot = v10 * (1.0f - wx) + v11 * wx;
        float val = top * (1.0f - wy) + bot * wy;
        sum += di[u] * val;
    }

    float bs = blockReduceSum256(sum);
    if (threadIdx.x == 0) g_pov[n * WTILES + tile] = bs;
}

// Kernel 3 v4: one block per BATCH (16 blocks, 256 threads). Weights in smem.
#define NW_QW1 512
#define NW_QW2 4096
#define NW_KW1 512
#define NW_KW2 4096
#define NW_EW1 8192
#define NW_EW2 64
#define NW_TOTAL (NW_QW1+NW_QW2+NW_KW1+NW_KW2+NW_EW1+NW_EW2)   // 17472 floats

__global__ void __launch_bounds__(256)
k_head(const float* __restrict__ na,
       const float* __restrict__ qW1, const float* __restrict__ qb1,
       const float* __restrict__ qW2, const float* __restrict__ qb2,
       const float* __restrict__ kW1, const float* __restrict__ kb1,
       const float* __restrict__ kW2, const float* __restrict__ kb2,
       const float* __restrict__ eW1, const float* __restrict__ eb1,
       const float* __restrict__ eW2, const float* __restrict__ eb2,
       float* __restrict__ out) {
    extern __shared__ float sw[];
    float* w_qW1 = sw;
    float* w_qW2 = w_qW1 + NW_QW1;
    float* w_kW1 = w_qW2 + NW_QW2;
    float* w_kW2 = w_kW1 + NW_KW1;
    float* w_eW1 = w_kW2 + NW_KW2;
    float* w_eW2 = w_eW1 + NW_EW1;

    __shared__ float s_mc[LAG], s_ov[LAG];
    __shared__ float s_dem;
    __shared__ float s_ego[8];
    __shared__ float s_feat[LAG][8];
    __shared__ float s_hq[64], s_q[64];
    __shared__ float s_hk[LAG][64], s_k[LAG][64], s_e[LAG][64];

    int b = blockIdx.x;
    int t = threadIdx.x;
    int lane = t & 31, warp = t >> 5;
    const float invHW = 1.0f / (float)HW;

    // Stage weights (256 threads, float4 = 1024 floats per sweep)
    for (int i = t * 4; i < NW_QW1;  i += 1024) *(float4*)(w_qW1 + i) = *(const float4*)(qW1 + i);
    for (int i = t * 4; i < NW_KW1;  i += 1024) *(float4*)(w_kW1 + i) = *(const float4*)(kW1 + i);
    for (int i = t * 4; i < NW_QW2;  i += 1024) *(float4*)(w_qW2 + i) = *(const float4*)(qW2 + i);
    for (int i = t * 4; i < NW_KW2;  i += 1024) *(float4*)(w_kW2 + i) = *(const float4*)(kW2 + i);
    for (int i = t * 4; i < NW_EW1;  i += 1024) *(float4*)(w_eW1 + i) = *(const float4*)(eW1 + i);
    if (t < 16) *(float4*)(w_eW2 + t * 4) = *(const float4*)(eW2 + t * 4);

    // Reduce partials: warp w handles row l=w (mean_conf 72 + overlap 144); warp 0 also demand.
    {
        int l = warp;
        int n = b * LAG + l;
        float mc = 0.0f, ov = 0.0f, dm = 0.0f;
        for (int i = lane; i < CTILES; i += 32) mc += g_pmc[n * CTILES + i];
        for (int i = lane; i < WTILES; i += 32) ov += g_pov[n * WTILES + i];
        if (warp == 0)
            for (int i = lane; i < CTILES; i += 32) dm += g_pdem[b * CTILES + i];
        for (int o = 16; o > 0; o >>= 1) {
            mc += __shfl_down_sync(0xffffffffu, mc, o);
            ov += __shfl_down_sync(0xffffffffu, ov, o);
            dm += __shfl_down_sync(0xffffffffu, dm, o);
        }
        if (lane == 0) {
            s_mc[l] = mc * invHW;
            s_ov[l] = ov * invHW;
            if (warp == 0) s_dem = dm * invHW;
        }
    }
    __syncthreads();

    // Features: thread l < 8 builds feat row; thread 8 builds ego
    if (t < LAG) {
        int l = t;
        const float* A = na + (size_t)((b * LAG + 0) * LAG + l) * 6;
        float dx = A[2], dy = A[5];
        float dist = sqrtf(dx * dx + dy * dy);
        const float* D  = na + (size_t)((b * LAG + l) * LAG + l) * 6;
        const float* D0 = na + (size_t)((b * LAG + 0) * LAG + 0) * 6;
        float yaw  = atan2f(D[3], D[0]);
        float yaw0 = atan2f(D0[3], D0[0]);
        float d = yaw0 - yaw;
        s_feat[l][0] = s_mc[l]; s_feat[l][1] = s_ov[l];
        s_feat[l][2] = dx;      s_feat[l][3] = dy;
        s_feat[l][4] = cosf(d); s_feat[l][5] = sinf(d);
        s_feat[l][6] = dist;    s_feat[l][7] = s_dem;
    } else if (t == LAG) {
        float dm = s_dem, mc0 = s_mc[0];
        s_ego[0] = mc0; s_ego[1] = dm; s_ego[2] = 0.0f; s_ego[3] = 0.0f;
        s_ego[4] = 1.0f; s_ego[5] = 0.0f; s_ego[6] = 0.0f; s_ego[7] = dm;
    }
    __syncthreads();

    // Layer 1: q (t<64) + k (2 outs/thread over 8 rows x 64)
    if (t < 64) {
        float acc = qb1[t];
        #pragma unroll
        for (int i = 0; i < 8; i++) acc = fmaf(s_ego[i], w_qW1[i * 64 + t], acc);
        s_hq[t] = fmaxf(acc, 0.0f);
    }
    #pragma unroll
    for (int c = 0; c < 2; c++) {
        int o = t + c * 256;
        int r = o >> 6, j = o & 63;
        float acc = kb1[j];
        #pragma unroll
        for (int i = 0; i < 8; i++) acc = fmaf(s_feat[r][i], w_kW1[i * 64 + j], acc);
        s_hk[r][j] = fmaxf(acc, 0.0f);
    }
    __syncthreads();

    // Layer 2
    if (t < 64) {
        float acc = qb2[t];
        #pragma unroll
        for (int i = 0; i < 64; i++) acc = fmaf(s_hq[i], w_qW2[i * 64 + t], acc);
        s_q[t] = acc;
    }
    #pragma unroll
    for (int c = 0; c < 2; c++) {
        int o = t + c * 256;
        int r = o >> 6, j = o & 63;
        float acc = kb2[j];
        #pragma unroll
        for (int i = 0; i < 64; i++) acc = fmaf(s_hk[r][i], w_kW2[i * 64 + j], acc);
        s_k[r][j] = acc;
    }
    __syncthreads();

    // e-layer hidden: input [q, k[r]] (128-wide), 2 outs/thread
    #pragma unroll
    for (int c = 0; c < 2; c++) {
        int o = t + c * 256;
        int r = o >> 6, j = o & 63;
        float acc = eb1[j];
        #pragma unroll
        for (int i = 0; i < 64; i++) acc = fmaf(s_q[i],    w_eW1[i * 64 + j], acc);
        #pragma unroll
        for (int i = 0; i < 64; i++) acc = fmaf(s_k[r][i], w_eW1[(64 + i) * 64 + j], acc);
        s_e[r][j] = fmaxf(acc, 0.0f);
    }
    __syncthreads();

    // Final: warp w computes logit for row l=w (dot of 64 with eW2)
    {
        int l = warp;
        float acc = fmaf(s_e[l][lane], w_eW2[lane], s_e[l][lane + 32] * w_eW2[lane + 32]);
        for (int o = 16; o > 0; o >>= 1) acc += __shfl_down_sync(0xffffffffu, acc, o);
        if (lane == 0) {
            float logit = acc + eb2[0];
            if (l == 0) logit = NEGV;
            float s = 1.0f / (1.0f + expf(-logit));
            out[b * LAG + l] = fminf(fmaxf(s, 0.0f), 1.0f);
        }
    }
}

extern "C" void kernel_launch(void* const* d_in, const int* in_sizes, int n_in,
                              void* d_out, int out_size) {
    const float* psm  = (const float*)d_in[0];
    const float* req  = (const float*)d_in[1];
    const float* na   = (const float*)d_in[2];
    // d_in[3] = record_len (unused, always L)
    const float* qW1 = (const float*)d_in[4];
    const float* qb1 = (const float*)d_in[5];
    const float* qW2 = (const float*)d_in[6];
    const float* qb2 = (const float*)d_in[7];
    const float* kW1 = (const float*)d_in[8];
    const float* kb1 = (const float*)d_in[9];
    const float* kW2 = (const float*)d_in[10];
    const float* kb2 = (const float*)d_in[11];
    const float* eW1 = (const float*)d_in[12];
    const float* eb1 = (const float*)d_in[13];
    const float* eW2 = (const float*)d_in[14];
    const float* eb2 = (const float*)d_in[15];
    float* out = (float*)d_out;

    cudaFuncSetAttribute(k_head, cudaFuncAttributeMaxDynamicSharedMemorySize,
                         NW_TOTAL * 4);

    k_conf<<<SUMN * CTILES, 256>>>(psm, req);
    k_warp<<<SUMN * WTILES, 256>>>(req, na);
    k_head<<<BATCH, 256, NW_TOTAL * 4>>>(na, qW1, qb1, qW2, qb2, kW1, kb1, kW2, kb2,
                                         eW1, eb1, eW2, eb2, out);
}